// round 15
// baseline (speedup 1.0000x reference)
#include <cuda_runtime.h>
#include <cuda_fp16.h>
#include <cstdint>

#define NNODES 100000
#define NEDGES 640000
#define NREL   16
#define TILE   128
#define MAXT   (NEDGES / TILE + NREL)
#define NTILES_SELF ((NNODES + TILE - 1) / TILE)

// SMEM layout (dynamic): fp16 panels, then meta. Epilogue fp32 128x128 tile (64KB) overlays panels.
#define SA_H   0
#define SB_H   16384
#define SRC_OFF 65536
#define DST_OFF 66048
#define BIAS_OFF 66560
#define SMEM_SZ 67072

// ---------------- scratch ----------------
__device__ int g_cnt[NREL];
__device__ int g_cur[NREL * 32];
__device__ int g_tile_pre[NREL + 1];
__device__ int g_base[NREL];
__device__ int g_src[NEDGES + NREL * TILE];
__device__ int g_dst[NEDGES + NREL * TILE];
__device__ uint4 g_xh[NNODES * 16];         // x fp16 [node][128]
__device__ uint4 g_wt[NREL * 2048];         // W^T fp16 [r][n][k]
__device__ uint4 g_sw[2048];                // self W^T fp16 [n][k]

// ---------------- helpers ----------------
static __device__ __forceinline__ uint32_t smem_u32(const void* p) {
    uint32_t a;
    asm("{ .reg .u64 t; cvta.to.shared.u64 t, %1; cvt.u32.u64 %0, t; }" : "=r"(a) : "l"(p));
    return a;
}
static __device__ __forceinline__ void ldsm4(uint32_t* r, uint32_t addr) {
    asm volatile("ldmatrix.sync.aligned.m8n8.x4.shared.b16 {%0,%1,%2,%3}, [%4];"
                 : "=r"(r[0]), "=r"(r[1]), "=r"(r[2]), "=r"(r[3]) : "r"(addr));
}
static __device__ __forceinline__ void mma16816(float* c, const uint32_t* a, const uint32_t* b) {
    asm volatile("mma.sync.aligned.m16n8k16.row.col.f32.f16.f16.f32 "
                 "{%0,%1,%2,%3}, {%4,%5,%6,%7}, {%8,%9}, {%0,%1,%2,%3};"
                 : "+f"(c[0]), "+f"(c[1]), "+f"(c[2]), "+f"(c[3])
                 : "r"(a[0]), "r"(a[1]), "r"(a[2]), "r"(a[3]), "r"(b[0]), "r"(b[1]));
}
static __device__ __forceinline__ void red4(float* p, float a, float b, float c, float d) {
    asm volatile("red.global.add.v4.f32 [%0], {%1,%2,%3,%4};"
                 :: "l"(p), "f"(a), "f"(b), "f"(c), "f"(d) : "memory");
}

// ---------------- merged init: zero counters + all packs (one launch) ----------------
#define NB_PX (NNODES * 128 / 1024)            // 12500
#define NB_PW (NREL * 128 * 128 / 1024)        // 256
#define NB_PS (128 * 128 / 1024)               // 16
__global__ void k_init(const float* __restrict__ x, const float* __restrict__ rw,
                       const float* __restrict__ sw) {
    int b = blockIdx.x;
    if (b < NB_PX) {
        int i = b * 1024 + threadIdx.x;
        reinterpret_cast<__half*>(g_xh)[i] = __float2half_rn(x[i]);
    } else if (b < NB_PX + NB_PW) {
        int i = (b - NB_PX) * 1024 + threadIdx.x;
        int k = i & 127, n = (i >> 7) & 127, r = i >> 14;
        reinterpret_cast<__half*>(g_wt)[i] = __float2half_rn(rw[((size_t)r * 128 + k) * 128 + n]);
    } else if (b < NB_PX + NB_PW + NB_PS) {
        int i = (b - NB_PX - NB_PW) * 1024 + threadIdx.x;
        int k = i & 127, n = i >> 7;
        reinterpret_cast<__half*>(g_sw)[i] = __float2half_rn(sw[k * 128 + n]);
    } else {
        if (threadIdx.x < NREL) g_cnt[threadIdx.x] = 0;
    }
}

// ---------------- histogram ----------------
__global__ __launch_bounds__(1024) void k_hist(const int* __restrict__ et) {
    __shared__ int wcnt[32 * NREL];
    int tid = threadIdx.x;
    if (tid < 32 * NREL) wcnt[tid] = 0;
    __syncthreads();
    int e = blockIdx.x * 1024 + tid;
    int r = et[e] & (NREL - 1);
    unsigned m = __match_any_sync(0xffffffffu, r);
    if ((tid & 31) == __ffs(m) - 1) wcnt[(tid >> 5) * NREL + r] = __popc(m);
    __syncthreads();
    if (tid < NREL) {
        int s = 0;
        for (int w = 0; w < 32; w++) s += wcnt[w * NREL + tid];
        atomicAdd(&g_cnt[tid], s);
    }
}

// ---------------- plan ----------------
__global__ void k_plan() {
    if (threadIdx.x == 0) {
        int tacc = 0, bacc = 0;
        for (int r = 0; r < NREL; r++) {
            g_base[r] = bacc;
            g_cur[r * 32] = bacc;
            g_tile_pre[r] = tacc;
            int nt = (g_cnt[r] + TILE - 1) / TILE;
            tacc += nt;
            bacc += nt * TILE;
        }
        g_tile_pre[NREL] = tacc;
    }
}

// ---------------- scatter (one global atomic per block per relation) ----------------
__global__ __launch_bounds__(1024) void k_scatter(const int* __restrict__ ei,
                                                  const int* __restrict__ et) {
    __shared__ int wcnt[32 * NREL];
    __shared__ int gb[NREL];
    int tid = threadIdx.x;
    if (tid < 32 * NREL) wcnt[tid] = 0;
    __syncthreads();
    int e = blockIdx.x * 1024 + tid;
    int r = et[e] & (NREL - 1);
    int lane = tid & 31, w = tid >> 5;
    unsigned m = __match_any_sync(0xffffffffu, r);
    int rank = __popc(m & ((1u << lane) - 1u));
    if (lane == __ffs(m) - 1) wcnt[w * NREL + r] = __popc(m);
    __syncthreads();
    if (tid < NREL) {
        int s = 0;
        for (int ww = 0; ww < 32; ww++) {
            int t0 = wcnt[ww * NREL + tid];
            wcnt[ww * NREL + tid] = s;
            s += t0;
        }
        gb[tid] = atomicAdd(&g_cur[tid * 32], s);
    }
    __syncthreads();
    int slot = gb[r] + wcnt[w * NREL + r] + rank;
    unsigned s = (unsigned)ei[e];
    unsigned d = (unsigned)ei[NEDGES + e];
    g_src[slot] = (s < NNODES) ? (int)s : 0;
    g_dst[slot] = (d < NNODES) ? (int)d : 0;
}

// ---------------- GEMM core: one K-half (64), single-pass fp16 ----------------
static __device__ __forceinline__ void gemm_khalf(uint32_t aH, uint32_t bH,
                                                  int lane, int wm, int wn,
                                                  float acc[2][8][4]) {
    int arow0 = wm + (lane & 15);
    int acp = lane >> 4;
    int brow_in = ((lane >> 4) << 3) + (lane & 7);
    int bcp = (lane >> 3) & 1;
#pragma unroll
    for (int ks = 0; ks < 4; ks++) {
        uint32_t ah[2][4];
#pragma unroll
        for (int i = 0; i < 2; i++) {
            int r = arow0 + i * 16;
            uint32_t off = (uint32_t)(r * 128 + (((ks * 2 + acp) ^ (r & 7)) << 4));
            ldsm4(ah[i], aH + off);
        }
#pragma unroll
        for (int j2 = 0; j2 < 4; j2++) {
            int rn = wn + j2 * 16 + brow_in;
            uint32_t boff = (uint32_t)(rn * 128 + (((ks * 2 + bcp) ^ (rn & 7)) << 4));
            uint32_t bh[4];
            ldsm4(bh, bH + boff);
#pragma unroll
            for (int i = 0; i < 2; i++)
#pragma unroll
                for (int jj = 0; jj < 2; jj++)
                    mma16816(acc[i][j2 * 2 + jj], ah[i], bh + jj * 2);
        }
    }
}

// store acc fragments into fp32 SMEM tile (overlays panels), swizzled 16B chunks
static __device__ __forceinline__ void acc_to_smem(char* smem, int lane, int wm, int wn,
                                                   float acc[2][8][4]) {
#pragma unroll
    for (int i = 0; i < 2; i++)
#pragma unroll
        for (int j = 0; j < 8; j++)
#pragma unroll
            for (int h = 0; h < 2; h++) {
                int r = wm + i * 16 + (lane >> 2) + h * 8;
                int col = wn + j * 8 + (lane & 3) * 2;
                int byte = col * 4;
                int c = byte >> 4;
                uint32_t addr = (uint32_t)(r * 512 + ((c ^ (r & 31)) << 4) + (byte & 15));
                *reinterpret_cast<float2*>(smem + addr) =
                    make_float2(acc[i][j][h * 2], acc[i][j][h * 2 + 1]);
            }
}

// ---------------- neighbor: gather - HMMA - scatter-RED (A-prefetch pipelined) ------
__global__ __launch_bounds__(256, 2) void k_neighbor(float* __restrict__ out) {
    extern __shared__ char smem[];
    int t = blockIdx.x;
    if (t >= g_tile_pre[NREL]) return;
    int rel = 0;
#pragma unroll
    for (int r = 1; r < NREL; r++)
        if (t >= g_tile_pre[r]) rel = r;
    int tin = t - g_tile_pre[rel];
    int base = g_base[rel] + tin * TILE;
    int rows = g_cnt[rel] - tin * TILE;
    if (rows > TILE) rows = TILE;

    int tid = threadIdx.x;
    int lane = tid & 31, wid = tid >> 5;
    int wm = (wid >> 1) * 32, wn = (wid & 1) * 64;
    int* s_src = reinterpret_cast<int*>(smem + SRC_OFF);
    int* s_dst = reinterpret_cast<int*>(smem + DST_OFF);
    if (tid < TILE) {
        bool ok = tid < rows;
        s_src[tid] = ok ? g_src[base + tid] : 0;
        s_dst[tid] = ok ? g_dst[base + tid] : 0;
    }
    __syncthreads();

    uint32_t sb = smem_u32(smem);
    float acc[2][8][4];
#pragma unroll
    for (int i = 0; i < 2; i++)
#pragma unroll
        for (int j = 0; j < 8; j++)
#pragma unroll
            for (int q = 0; q < 4; q++) acc[i][j][q] = 0.f;

    int gr = tid >> 1, p0 = (tid & 1) * 4;
    uint4* dAh = reinterpret_cast<uint4*>(smem + SA_H);
    uint4* dBh = reinterpret_cast<uint4*>(smem + SB_H);

    const uint4* xrow = g_xh + (size_t)s_src[gr] * 16;
    const uint4* wrow = g_wt + (size_t)rel * 2048 + (size_t)gr * 16;

    // prologue: prefetch kc=0 A chunks into registers
    uint4 areg[4];
#pragma unroll
    for (int c = 0; c < 4; c++) areg[c] = __ldg(xrow + p0 + c);

#pragma unroll
    for (int kc = 0; kc < 2; kc++) {
        if (kc) __syncthreads();           // previous gemm done reading panels
#pragma unroll
        for (int c = 0; c < 4; c++) {
            int ch = p0 + c;
            int ph = ch ^ (gr & 7);
            dAh[gr * 8 + ph] = areg[c];
            dBh[gr * 8 + ph] = wrow[kc * 8 + ch];   // LDG (L1-cached) -> STS
        }
        __syncthreads();
        if (kc == 0) {                     // prefetch kc=1 A while gemm(kc=0) runs
#pragma unroll
            for (int c = 0; c < 4; c++) areg[c] = __ldg(xrow + 8 + p0 + c);
        }
        gemm_khalf(sb + SA_H, sb + SB_H, lane, wm, wn, acc);
    }

    __syncthreads();
    acc_to_smem(smem, lane, wm, wn, acc);
    __syncthreads();

    int r = tid >> 1, half = tid & 1;
    if (r < rows) {
        float* pdst = out + (size_t)s_dst[r] * 128;
#pragma unroll
        for (int i = 0; i < 16; i++) {
            int cL = half * 16 + i;
            int phys = cL ^ (r & 31);
            float4 v = *reinterpret_cast<float4*>(smem + r * 512 + phys * 16);
            red4(pdst + cL * 4, v.x, v.y, v.z, v.w);
        }
    }
}

// ---------------- self GEMM: out = x @ Ws + bias (runs BEFORE neighbor) ----------------
__global__ __launch_bounds__(256, 2) void k_self(const float* __restrict__ bias,
                                                 float* __restrict__ out) {
    extern __shared__ char smem[];
    int tid = threadIdx.x;
    int lane = tid & 31, wid = tid >> 5;
    int wm = (wid >> 1) * 32, wn = (wid & 1) * 64;
    int rowbase = blockIdx.x * TILE;

    float* sBias = reinterpret_cast<float*>(smem + BIAS_OFF);
    if (tid < 128) sBias[tid] = bias[tid];

    uint32_t sb = smem_u32(smem);
    float acc[2][8][4];
#pragma unroll
    for (int i = 0; i < 2; i++)
#pragma unroll
        for (int j = 0; j < 8; j++)
#pragma unroll
            for (int q = 0; q < 4; q++) acc[i][j][q] = 0.f;

    int gr = tid >> 1, p0 = (tid & 1) * 4;
    int node = rowbase + gr;
    if (node >= NNODES) node = NNODES - 1;
    uint4* dAh = reinterpret_cast<uint4*>(smem + SA_H);
    uint4* dBh = reinterpret_cast<uint4*>(smem + SB_H);

    const uint4* xrow = g_xh + (size_t)node * 16;
    const uint4* wrow = g_sw + (size_t)gr * 16;

    uint4 areg[4];
#pragma unroll
    for (int c = 0; c < 4; c++) areg[c] = __ldg(xrow + p0 + c);

#pragma unroll
    for (int kc = 0; kc < 2; kc++) {
        __syncthreads();
#pragma unroll
        for (int c = 0; c < 4; c++) {
            int ch = p0 + c;
            int ph = ch ^ (gr & 7);
            dAh[gr * 8 + ph] = areg[c];
            dBh[gr * 8 + ph] = wrow[kc * 8 + ch];
        }
        __syncthreads();
        if (kc == 0) {
#pragma unroll
            for (int c = 0; c < 4; c++) areg[c] = __ldg(xrow + 8 + p0 + c);
        }
        gemm_khalf(sb + SA_H, sb + SB_H, lane, wm, wn, acc);
    }

    __syncthreads();
    acc_to_smem(smem, lane, wm, wn, acc);
    __syncthreads();

    int r = tid >> 1, half = tid & 1;
    int row = rowbase + r;
    if (row < NNODES) {
        float4* out4 = reinterpret_cast<float4*>(out) + (size_t)row * 32;
        const float4* b4 = reinterpret_cast<const float4*>(sBias);
#pragma unroll
        for (int i = 0; i < 16; i++) {
            int cL = half * 16 + i;
            int phys = cL ^ (r & 31);
            float4 v = *reinterpret_cast<float4*>(smem + r * 512 + phys * 16);
            float4 bb = b4[cL];
            out4[cL] = make_float4(v.x + bb.x, v.y + bb.y, v.z + bb.z, v.w + bb.w);
        }
    }
}

// ---------------- ReLU ----------------
__global__ void k_relu(float* __restrict__ out) {
    int n = NNODES * 128 / 4;
    float4* o4 = reinterpret_cast<float4*>(out);
    for (int i = blockIdx.x * blockDim.x + threadIdx.x; i < n;
         i += gridDim.x * blockDim.x) {
        float4 v = o4[i];
        v.x = fmaxf(v.x, 0.f); v.y = fmaxf(v.y, 0.f);
        v.z = fmaxf(v.z, 0.f); v.w = fmaxf(v.w, 0.f);
        o4[i] = v;
    }
}

// ---------------- launch ----------------
extern "C" void kernel_launch(void* const* d_in, const int* in_sizes, int n_in,
                              void* d_out, int out_size) {
    const float* x    = (const float*)d_in[0];
    const int*   ei   = (const int*)d_in[1];
    const int*   et   = (const int*)d_in[2];
    const float* rw   = (const float*)d_in[3];
    const float* sw   = (const float*)d_in[4];
    const float* bias = (const float*)d_in[5];
    float* out = (float*)d_out;

    cudaFuncSetAttribute(k_neighbor, cudaFuncAttributeMaxDynamicSharedMemorySize, SMEM_SZ);
    cudaFuncSetAttribute(k_self, cudaFuncAttributeMaxDynamicSharedMemorySize, SMEM_SZ);

    k_init<<<NB_PX + NB_PW + NB_PS + 1, 1024>>>(x, rw, sw);
    k_hist<<<NEDGES / 1024, 1024>>>(et);
    k_plan<<<1, 1>>>();
    k_scatter<<<NEDGES / 1024, 1024>>>(ei, et);
    k_self<<<NTILES_SELF, 256, SMEM_SZ>>>(bias, out);
    k_neighbor<<<MAXT, 256, SMEM_SZ>>>(out);
    k_relu<<<1024, 256>>>(out);
}

// round 16
// speedup vs baseline: 1.4871x; 1.4871x over previous
#include <cuda_runtime.h>
#include <cuda_fp16.h>
#include <cstdint>

#define NNODES 100000
#define NEDGES 640000
#define NREL   16
#define TILE   128
#define MAXT   (NEDGES / TILE + NREL)
#define NTILES_SELF ((NNODES + TILE - 1) / TILE)

// SMEM layout (dynamic): fp16 panels, then meta. Epilogue fp32 128x128 tile (64KB) overlays panels.
#define SA_H   0
#define SB_H   16384
#define SRC_OFF 65536
#define DST_OFF 66048
#define BIAS_OFF 66560
#define SMEM_SZ 67072

// ---------------- scratch ----------------
__device__ int g_cnt[NREL];
__device__ int g_cur[NREL * 32];
__device__ int g_tile_pre[NREL + 1];
__device__ int g_base[NREL];
__device__ int g_src[NEDGES + NREL * TILE];
__device__ int g_dst[NEDGES + NREL * TILE];
__device__ uint4 g_xh[NNODES * 16];         // x fp16 [node][128]
__device__ uint4 g_wt[NREL * 2048];         // W^T fp16 [r][n][k]
__device__ uint4 g_sw[2048];                // self W^T fp16 [n][k]

// ---------------- helpers ----------------
static __device__ __forceinline__ uint32_t smem_u32(const void* p) {
    uint32_t a;
    asm("{ .reg .u64 t; cvta.to.shared.u64 t, %1; cvt.u32.u64 %0, t; }" : "=r"(a) : "l"(p));
    return a;
}
static __device__ __forceinline__ void ldsm4(uint32_t* r, uint32_t addr) {
    asm volatile("ldmatrix.sync.aligned.m8n8.x4.shared.b16 {%0,%1,%2,%3}, [%4];"
                 : "=r"(r[0]), "=r"(r[1]), "=r"(r[2]), "=r"(r[3]) : "r"(addr));
}
static __device__ __forceinline__ void mma16816(float* c, const uint32_t* a, const uint32_t* b) {
    asm volatile("mma.sync.aligned.m16n8k16.row.col.f32.f16.f16.f32 "
                 "{%0,%1,%2,%3}, {%4,%5,%6,%7}, {%8,%9}, {%0,%1,%2,%3};"
                 : "+f"(c[0]), "+f"(c[1]), "+f"(c[2]), "+f"(c[3])
                 : "r"(a[0]), "r"(a[1]), "r"(a[2]), "r"(a[3]), "r"(b[0]), "r"(b[1]));
}
static __device__ __forceinline__ void red4(float* p, float a, float b, float c, float d) {
    asm volatile("red.global.add.v4.f32 [%0], {%1,%2,%3,%4};"
                 :: "l"(p), "f"(a), "f"(b), "f"(c), "f"(d) : "memory");
}

// ---------------- merged init: zero counters + all packs (one launch) ----------------
#define NB_PX (NNODES * 128 / 1024)            // 12500
#define NB_PW (NREL * 128 * 128 / 1024)        // 256
#define NB_PS (128 * 128 / 1024)               // 16
__global__ void k_init(const float* __restrict__ x, const float* __restrict__ rw,
                       const float* __restrict__ sw) {
    int b = blockIdx.x;
    if (b < NB_PX) {
        int i = b * 1024 + threadIdx.x;
        reinterpret_cast<__half*>(g_xh)[i] = __float2half_rn(x[i]);
    } else if (b < NB_PX + NB_PW) {
        int i = (b - NB_PX) * 1024 + threadIdx.x;
        int k = i & 127, n = (i >> 7) & 127, r = i >> 14;
        reinterpret_cast<__half*>(g_wt)[i] = __float2half_rn(rw[((size_t)r * 128 + k) * 128 + n]);
    } else if (b < NB_PX + NB_PW + NB_PS) {
        int i = (b - NB_PX - NB_PW) * 1024 + threadIdx.x;
        int k = i & 127, n = i >> 7;
        reinterpret_cast<__half*>(g_sw)[i] = __float2half_rn(sw[k * 128 + n]);
    } else {
        if (threadIdx.x < NREL) g_cnt[threadIdx.x] = 0;
    }
}

// ---------------- histogram ----------------
__global__ __launch_bounds__(1024) void k_hist(const int* __restrict__ et) {
    __shared__ int wcnt[32 * NREL];
    int tid = threadIdx.x;
    if (tid < 32 * NREL) wcnt[tid] = 0;
    __syncthreads();
    int e = blockIdx.x * 1024 + tid;
    int r = et[e] & (NREL - 1);
    unsigned m = __match_any_sync(0xffffffffu, r);
    if ((tid & 31) == __ffs(m) - 1) wcnt[(tid >> 5) * NREL + r] = __popc(m);
    __syncthreads();
    if (tid < NREL) {
        int s = 0;
        for (int w = 0; w < 32; w++) s += wcnt[w * NREL + tid];
        atomicAdd(&g_cnt[tid], s);
    }
}

// ---------------- plan ----------------
__global__ void k_plan() {
    if (threadIdx.x == 0) {
        int tacc = 0, bacc = 0;
        for (int r = 0; r < NREL; r++) {
            g_base[r] = bacc;
            g_cur[r * 32] = bacc;
            g_tile_pre[r] = tacc;
            int nt = (g_cnt[r] + TILE - 1) / TILE;
            tacc += nt;
            bacc += nt * TILE;
        }
        g_tile_pre[NREL] = tacc;
    }
}

// ---------------- scatter (one global atomic per block per relation) ----------------
__global__ __launch_bounds__(1024) void k_scatter(const int* __restrict__ ei,
                                                  const int* __restrict__ et) {
    __shared__ int wcnt[32 * NREL];
    __shared__ int gb[NREL];
    int tid = threadIdx.x;
    if (tid < 32 * NREL) wcnt[tid] = 0;
    __syncthreads();
    int e = blockIdx.x * 1024 + tid;
    int r = et[e] & (NREL - 1);
    int lane = tid & 31, w = tid >> 5;
    unsigned m = __match_any_sync(0xffffffffu, r);
    int rank = __popc(m & ((1u << lane) - 1u));
    if (lane == __ffs(m) - 1) wcnt[w * NREL + r] = __popc(m);
    __syncthreads();
    if (tid < NREL) {
        int s = 0;
        for (int ww = 0; ww < 32; ww++) {
            int t0 = wcnt[ww * NREL + tid];
            wcnt[ww * NREL + tid] = s;
            s += t0;
        }
        gb[tid] = atomicAdd(&g_cur[tid * 32], s);
    }
    __syncthreads();
    int slot = gb[r] + wcnt[w * NREL + r] + rank;
    unsigned s = (unsigned)ei[e];
    unsigned d = (unsigned)ei[NEDGES + e];
    g_src[slot] = (s < NNODES) ? (int)s : 0;
    g_dst[slot] = (d < NNODES) ? (int)d : 0;
}

// ---------------- GEMM core: one K-half (64), single-pass fp16 ----------------
static __device__ __forceinline__ void gemm_khalf(uint32_t aH, uint32_t bH,
                                                  int lane, int wm, int wn,
                                                  float acc[2][8][4]) {
    int arow0 = wm + (lane & 15);
    int acp = lane >> 4;
    int brow_in = ((lane >> 4) << 3) + (lane & 7);
    int bcp = (lane >> 3) & 1;
#pragma unroll
    for (int ks = 0; ks < 4; ks++) {
        uint32_t ah[2][4];
#pragma unroll
        for (int i = 0; i < 2; i++) {
            int r = arow0 + i * 16;
            uint32_t off = (uint32_t)(r * 128 + (((ks * 2 + acp) ^ (r & 7)) << 4));
            ldsm4(ah[i], aH + off);
        }
#pragma unroll
        for (int j2 = 0; j2 < 4; j2++) {
            int rn = wn + j2 * 16 + brow_in;
            uint32_t boff = (uint32_t)(rn * 128 + (((ks * 2 + bcp) ^ (rn & 7)) << 4));
            uint32_t bh[4];
            ldsm4(bh, bH + boff);
#pragma unroll
            for (int i = 0; i < 2; i++)
#pragma unroll
                for (int jj = 0; jj < 2; jj++)
                    mma16816(acc[i][j2 * 2 + jj], ah[i], bh + jj * 2);
        }
    }
}

// store acc fragments into fp32 SMEM tile (overlays panels), swizzled 16B chunks
static __device__ __forceinline__ void acc_to_smem(char* smem, int lane, int wm, int wn,
                                                   float acc[2][8][4]) {
#pragma unroll
    for (int i = 0; i < 2; i++)
#pragma unroll
        for (int j = 0; j < 8; j++)
#pragma unroll
            for (int h = 0; h < 2; h++) {
                int r = wm + i * 16 + (lane >> 2) + h * 8;
                int col = wn + j * 8 + (lane & 3) * 2;
                int byte = col * 4;
                int c = byte >> 4;
                uint32_t addr = (uint32_t)(r * 512 + ((c ^ (r & 31)) << 4) + (byte & 15));
                *reinterpret_cast<float2*>(smem + addr) =
                    make_float2(acc[i][j][h * 2], acc[i][j][h * 2 + 1]);
            }
}

// ---------------- neighbor: gather - HMMA - scatter-RED ----------------
__global__ __launch_bounds__(256, 2) void k_neighbor(float* __restrict__ out) {
    extern __shared__ char smem[];
    int t = blockIdx.x;
    if (t >= g_tile_pre[NREL]) return;
    int rel = 0;
#pragma unroll
    for (int r = 1; r < NREL; r++)
        if (t >= g_tile_pre[r]) rel = r;
    int tin = t - g_tile_pre[rel];
    int base = g_base[rel] + tin * TILE;
    int rows = g_cnt[rel] - tin * TILE;
    if (rows > TILE) rows = TILE;

    int tid = threadIdx.x;
    int lane = tid & 31, wid = tid >> 5;
    int wm = (wid >> 1) * 32, wn = (wid & 1) * 64;
    int* s_src = reinterpret_cast<int*>(smem + SRC_OFF);
    int* s_dst = reinterpret_cast<int*>(smem + DST_OFF);
    if (tid < TILE) {
        bool ok = tid < rows;
        s_src[tid] = ok ? g_src[base + tid] : 0;
        s_dst[tid] = ok ? g_dst[base + tid] : 0;
    }

    uint32_t sb = smem_u32(smem);
    float acc[2][8][4];
#pragma unroll
    for (int i = 0; i < 2; i++)
#pragma unroll
        for (int j = 0; j < 8; j++)
#pragma unroll
            for (int q = 0; q < 4; q++) acc[i][j][q] = 0.f;

    int gr = tid >> 1, p0 = (tid & 1) * 4;
    uint4* dAh = reinterpret_cast<uint4*>(smem + SA_H);
    uint4* dBh = reinterpret_cast<uint4*>(smem + SB_H);

#pragma unroll
    for (int kc = 0; kc < 2; kc++) {
        __syncthreads();
        int node = s_src[gr];
        const uint4* xh = g_xh + (size_t)node * 16 + kc * 8;
        const uint4* wh = g_wt + (size_t)rel * 2048 + gr * 16 + kc * 8;
#pragma unroll
        for (int c = 0; c < 4; c++) {
            int ch = p0 + c;
            int ph = ch ^ (gr & 7);
            dAh[gr * 8 + ph] = xh[ch];
            dBh[gr * 8 + ph] = wh[ch];
        }
        __syncthreads();
        gemm_khalf(sb + SA_H, sb + SB_H, lane, wm, wn, acc);
    }

    __syncthreads();
    acc_to_smem(smem, lane, wm, wn, acc);
    __syncthreads();

    int r = tid >> 1, half = tid & 1;
    if (r < rows) {
        float* pdst = out + (size_t)s_dst[r] * 128;
#pragma unroll
        for (int i = 0; i < 16; i++) {
            int cL = half * 16 + i;
            int phys = cL ^ (r & 31);
            float4 v = *reinterpret_cast<float4*>(smem + r * 512 + phys * 16);
            red4(pdst + cL * 4, v.x, v.y, v.z, v.w);
        }
    }
}

// ---------------- self GEMM: out = x @ Ws + bias ----------------
__global__ __launch_bounds__(256, 2) void k_self(const float* __restrict__ bias,
                                                 float* __restrict__ out) {
    extern __shared__ char smem[];
    int tid = threadIdx.x;
    int lane = tid & 31, wid = tid >> 5;
    int wm = (wid >> 1) * 32, wn = (wid & 1) * 64;
    int rowbase = blockIdx.x * TILE;

    float* sBias = reinterpret_cast<float*>(smem + BIAS_OFF);
    if (tid < 128) sBias[tid] = bias[tid];

    uint32_t sb = smem_u32(smem);
    float acc[2][8][4];
#pragma unroll
    for (int i = 0; i < 2; i++)
#pragma unroll
        for (int j = 0; j < 8; j++)
#pragma unroll
            for (int q = 0; q < 4; q++) acc[i][j][q] = 0.f;

    int gr = tid >> 1, p0 = (tid & 1) * 4;
    int node = rowbase + gr;
    if (node >= NNODES) node = NNODES - 1;
    uint4* dAh = reinterpret_cast<uint4*>(smem + SA_H);
    uint4* dBh = reinterpret_cast<uint4*>(smem + SB_H);

#pragma unroll
    for (int kc = 0; kc < 2; kc++) {
        __syncthreads();
        const uint4* xh = g_xh + (size_t)node * 16 + kc * 8;
        const uint4* wh = g_sw + gr * 16 + kc * 8;
#pragma unroll
        for (int c = 0; c < 4; c++) {
            int ch = p0 + c;
            int ph = ch ^ (gr & 7);
            dAh[gr * 8 + ph] = xh[ch];
            dBh[gr * 8 + ph] = wh[ch];
        }
        __syncthreads();
        gemm_khalf(sb + SA_H, sb + SB_H, lane, wm, wn, acc);
    }

    __syncthreads();
    acc_to_smem(smem, lane, wm, wn, acc);
    __syncthreads();

    int r = tid >> 1, half = tid & 1;
    int row = rowbase + r;
    if (row < NNODES) {
        float4* out4 = reinterpret_cast<float4*>(out) + (size_t)row * 32;
        const float4* b4 = reinterpret_cast<const float4*>(sBias);
#pragma unroll
        for (int i = 0; i < 16; i++) {
            int cL = half * 16 + i;
            int phys = cL ^ (r & 31);
            float4 v = *reinterpret_cast<float4*>(smem + r * 512 + phys * 16);
            float4 bb = b4[cL];
            out4[cL] = make_float4(v.x + bb.x, v.y + bb.y, v.z + bb.z, v.w + bb.w);
        }
    }
}

// ---------------- ReLU ----------------
__global__ void k_relu(float* __restrict__ out) {
    int n = NNODES * 128 / 4;
    float4* o4 = reinterpret_cast<float4*>(out);
    for (int i = blockIdx.x * blockDim.x + threadIdx.x; i < n;
         i += gridDim.x * blockDim.x) {
        float4 v = o4[i];
        v.x = fmaxf(v.x, 0.f); v.y = fmaxf(v.y, 0.f);
        v.z = fmaxf(v.z, 0.f); v.w = fmaxf(v.w, 0.f);
        o4[i] = v;
    }
}

// ---------------- launch ----------------
extern "C" void kernel_launch(void* const* d_in, const int* in_sizes, int n_in,
                              void* d_out, int out_size) {
    const float* x    = (const float*)d_in[0];
    const int*   ei   = (const int*)d_in[1];
    const int*   et   = (const int*)d_in[2];
    const float* rw   = (const float*)d_in[3];
    const float* sw   = (const float*)d_in[4];
    const float* bias = (const float*)d_in[5];
    float* out = (float*)d_out;

    cudaFuncSetAttribute(k_neighbor, cudaFuncAttributeMaxDynamicSharedMemorySize, SMEM_SZ);
    cudaFuncSetAttribute(k_self, cudaFuncAttributeMaxDynamicSharedMemorySize, SMEM_SZ);

    k_init<<<NB_PX + NB_PW + NB_PS + 1, 1024>>>(x, rw, sw);
    k_hist<<<NEDGES / 1024, 1024>>>(et);
    k_plan<<<1, 1>>>();
    k_scatter<<<NEDGES / 1024, 1024>>>(ei, et);
    k_self<<<NTILES_SELF, 256, SMEM_SZ>>>(bias, out);
    k_neighbor<<<MAXT, 256, SMEM_SZ>>>(out);
    k_relu<<<1024, 256>>>(out);
}